// round 8
// baseline (speedup 1.0000x reference)
#include <cuda_runtime.h>
#include <cuda_bf16.h>
#include <stdint.h>
#include <math.h>

// Problem dims
#define Ln 512
#define Nn 256
#define DMSA 256
#define DPAIR 128
#define Hh 8
#define Dd 32
#define HD 256
#define NL (Nn*Ln)          // 131072
#define NDIM 8192           // (n,d) contraction dim
#define SCALING 0.17677669529663689f
#define EPSC 1e-5f

typedef __nv_bfloat16 bf16;

// ----------------------------------------------------------------------------
// Scratch (device globals). Aliasing:
//   g_bufA = msa_n (hi/lo)  then  v^T (hi/lo)
//   g_bufB = q (hi/lo)      then  o (hi/lo)
__device__ __align__(16) bf16 g_bufA_hi[33554432];
__device__ __align__(16) bf16 g_bufA_lo[33554432];
__device__ __align__(16) bf16 g_bufB_hi[33554432];
__device__ __align__(16) bf16 g_bufB_lo[33554432];
__device__ __align__(16) bf16 g_k_hi[33554432];   // [h][l][nd]
__device__ __align__(16) bf16 g_k_lo[33554432];
__device__ __align__(16) bf16 g_v_hi[33554432];   // [h][l][nd]
__device__ __align__(16) bf16 g_v_lo[33554432];
__device__ __align__(16) bf16 g_p_hi[2097152];    // [h][q][k]
__device__ __align__(16) bf16 g_p_lo[2097152];
__device__ __align__(16) bf16 g_wt_hi[327680];    // [1280][256]
__device__ __align__(16) bf16 g_wt_lo[327680];
__device__ float g_gate[33554432];                // [r=(n,l)][h*32+d]
__device__ float g_attn[2097152];                 // [h][q][k]
__device__ float g_bias[2097152];                 // [q][k][h]

// ----------------------------------------------------------------------------
__device__ __forceinline__ uint32_t s2u(const void* p){
    uint32_t a;
    asm("{ .reg .u64 t; cvta.to.shared.u64 t, %1; cvt.u32.u64 %0, t; }" : "=r"(a) : "l"(p));
    return a;
}
#define CP16(sa, gp) \
    asm volatile("cp.async.cg.shared.global [%0], [%1], 16;" :: "r"(sa), "l"(gp))
#define CPCOMMIT() asm volatile("cp.async.commit_group;" ::: "memory")
#define CPWAIT(n)  asm volatile("cp.async.wait_group %0;" :: "n"(n) : "memory")

__device__ __forceinline__ void ldsm4(uint32_t a, uint32_t r[4]){
    asm volatile("ldmatrix.sync.aligned.m8n8.x4.shared.b16 {%0,%1,%2,%3}, [%4];"
                 : "=r"(r[0]), "=r"(r[1]), "=r"(r[2]), "=r"(r[3]) : "r"(a));
}
__device__ __forceinline__ void mma16816(float c[4], const uint32_t a[4],
                                         uint32_t b0, uint32_t b1){
    asm volatile("mma.sync.aligned.m16n8k16.row.col.f32.bf16.bf16.f32 "
                 "{%0,%1,%2,%3}, {%4,%5,%6,%7}, {%8,%9}, {%0,%1,%2,%3};"
                 : "+f"(c[0]), "+f"(c[1]), "+f"(c[2]), "+f"(c[3])
                 : "r"(a[0]), "r"(a[1]), "r"(a[2]), "r"(a[3]), "r"(b0), "r"(b1));
}
__device__ __forceinline__ void split_store(bf16* hi, bf16* lo, size_t idx, float v){
    bf16 h = __float2bfloat16(v);
    hi[idx] = h;
    lo[idx] = __float2bfloat16(v - __bfloat162float(h));
}
__device__ __forceinline__ float fixf(float v){
    if (isnan(v)) return 0.f;
    if (isinf(v)) return v > 0.f ? 3.4028234663852886e38f : -3.4028234663852886e38f;
    return v;
}

// ----------------------------------------------------------------------------
// LayerNorm msa -> bufA (bf16 hi/lo)
__global__ void k_ln_msa(const float* __restrict__ msa,
                         const float* __restrict__ g,
                         const float* __restrict__ b){
    int warp = threadIdx.x >> 5, lane = threadIdx.x & 31;
    size_t row = (size_t)blockIdx.x * 8 + warp;
    const float* x = msa + row * DMSA;
    float v[8]; float s = 0.f;
    #pragma unroll
    for (int i = 0; i < 8; i++){ float t = fixf(x[lane + i*32]); v[i] = t; s += t; }
    #pragma unroll
    for (int o = 16; o; o >>= 1) s += __shfl_xor_sync(0xffffffffu, s, o);
    float mu = s * (1.f/256.f);
    float q = 0.f;
    #pragma unroll
    for (int i = 0; i < 8; i++){ float d0 = v[i] - mu; q += d0*d0; }
    #pragma unroll
    for (int o = 16; o; o >>= 1) q += __shfl_xor_sync(0xffffffffu, q, o);
    float rs = rsqrtf(q * (1.f/256.f) + EPSC);
    #pragma unroll
    for (int i = 0; i < 8; i++){
        int c = lane + i*32;
        float y = (v[i] - mu) * rs * g[c] + b[c];
        split_store(g_bufA_hi, g_bufA_lo, row*DMSA + c, y);
    }
}

// Weight transpose+split: g_wt[row=(z*256+j)][k] = W_z[k][j]
__global__ void k_conv_w(const float* __restrict__ wq, const float* __restrict__ wk,
                         const float* __restrict__ wv, const float* __restrict__ wg,
                         const float* __restrict__ wo){
    int row = blockIdx.x, kk = threadIdx.x;
    int z = row >> 8, j = row & 255;
    const float* src = (z==0)?wq:(z==1)?wk:(z==2)?wv:(z==3)?wg:wo;
    float v = src[kk*256 + j];
    split_store(g_wt_hi, g_wt_lo, (size_t)row*256 + kk, v);
}

// LayerNorm pair + bias GEMV
__global__ void k_pair_bias(const float* __restrict__ pair,
                            const float* __restrict__ g,
                            const float* __restrict__ b,
                            const float* __restrict__ wb){
    __shared__ float swb[Hh*DPAIR];
    for (int i = threadIdx.x; i < Hh*DPAIR; i += blockDim.x){
        int h = i / DPAIR, c = i % DPAIR;
        swb[i] = wb[c*Hh + h];
    }
    __syncthreads();
    int warp = threadIdx.x >> 5, lane = threadIdx.x & 31;
    size_t row = (size_t)blockIdx.x * 8 + warp;
    const float* x = pair + row * DPAIR;
    float v[4]; float s = 0.f;
    #pragma unroll
    for (int i = 0; i < 4; i++){ float t = fixf(x[lane + i*32]); v[i] = t; s += t; }
    #pragma unroll
    for (int o = 16; o; o >>= 1) s += __shfl_xor_sync(0xffffffffu, s, o);
    float mu = s * (1.f/128.f);
    float q = 0.f;
    #pragma unroll
    for (int i = 0; i < 4; i++){ float d0 = v[i] - mu; q += d0*d0; }
    #pragma unroll
    for (int o = 16; o; o >>= 1) q += __shfl_xor_sync(0xffffffffu, q, o);
    float rs = rsqrtf(q * (1.f/128.f) + EPSC);
    float acc[8] = {};
    #pragma unroll
    for (int i = 0; i < 4; i++){
        int c = lane + i*32;
        float pn = (v[i] - mu) * rs * g[c] + b[c];
        #pragma unroll
        for (int h = 0; h < 8; h++) acc[h] += pn * swb[h*DPAIR + c];
    }
    #pragma unroll
    for (int h = 0; h < 8; h++)
        #pragma unroll
        for (int o = 16; o; o >>= 1) acc[h] += __shfl_xor_sync(0xffffffffu, acc[h], o);
    float outv = 0.f;
    #pragma unroll
    for (int h = 0; h < 8; h++) if (lane == h) outv = acc[h];
    if (lane < 8) g_bias[row*Hh + lane] = outv;
}

// Transpose V: [h][l][nd] -> [h][nd][l] into bufA
__global__ void k_transpose_v(){
    __shared__ bf16 tile[32][33];
    int head = blockIdx.z >> 1, arr = blockIdx.z & 1;
    const bf16* src = (arr ? g_v_lo : g_v_hi) + (size_t)head * Ln * NDIM;
    bf16* dst = (arr ? g_bufA_lo : g_bufA_hi) + (size_t)head * NDIM * Ln;
    int nd0 = blockIdx.x * 32, l0 = blockIdx.y * 32;
    #pragma unroll
    for (int yy = 0; yy < 4; yy++)
        tile[threadIdx.y + yy*8][threadIdx.x] =
            src[(size_t)(l0 + threadIdx.y + yy*8) * NDIM + nd0 + threadIdx.x];
    __syncthreads();
    #pragma unroll
    for (int yy = 0; yy < 4; yy++)
        dst[(size_t)(nd0 + threadIdx.y + yy*8) * Ln + l0 + threadIdx.x] =
            tile[threadIdx.x][threadIdx.y + yy*8];
}

// Softmax over k with bias + mask; writes P as bf16 hi/lo
__global__ void k_softmax(const int* __restrict__ mask){
    int h = blockIdx.x >> 9, q = blockIdx.x & (Ln-1);
    const float* row = g_attn + ((size_t)h*Ln + q)*Ln;
    bool padq = (mask[q] == 0);
    int t = threadIdx.x;
    int k0 = t, k1 = t + 256;
    float v0 = (padq || mask[k0] == 0) ? -1e9f : row[k0] + g_bias[((size_t)q*Ln + k0)*Hh + h];
    float v1 = (padq || mask[k1] == 0) ? -1e9f : row[k1] + g_bias[((size_t)q*Ln + k1)*Hh + h];
    __shared__ float red[256];
    red[t] = fmaxf(v0, v1); __syncthreads();
    for (int s = 128; s > 0; s >>= 1){ if (t < s) red[t] = fmaxf(red[t], red[t+s]); __syncthreads(); }
    float m = red[0]; __syncthreads();
    float e0 = expf(v0 - m), e1 = expf(v1 - m);
    red[t] = e0 + e1; __syncthreads();
    for (int s = 128; s > 0; s >>= 1){ if (t < s) red[t] += red[t+s]; __syncthreads(); }
    float inv = 1.f / red[0];
    size_t base = ((size_t)h*Ln + q)*Ln;
    split_store(g_p_hi, g_p_lo, base + k0, e0*inv);
    split_store(g_p_hi, g_p_lo, base + k1, e1*inv);
}

// ----------------------------------------------------------------------------
// Warp-MMA GEMM. MODE: 0=QKVG, 1=attn logits, 2=AV, 3=out-proj
// D[BM=128, BN=64] = A[M,K] @ B[N,K]^T,  A/B bf16 hi/lo K-major.
// 8 warps: 4(M) x 2(N), each 32x32.  BK=32, 3-stage cp.async pipeline,
// ONE __syncthreads per iteration (CUTLASS multistage discipline).
// SMEM row stride: 40 bf16 (80 B, 16B-aligned rows; i*20 words mod 32 distinct
// over 8 rows -> conflict-free ldmatrix).
#define RS   40
#define AELE 5120             // 128*40
#define BELE 2560             // 64*40
#define BUFE 15360            // Ah+Al+Bh+Bl elems per stage
#define STAGES 3
#define SMEMB (STAGES*BUFE*2) // 92160 bytes

template<int MODE>
__global__ __launch_bounds__(256, 2) void k_mma(const int* __restrict__ mask,
                                                const float* __restrict__ bg,
                                                const float* __restrict__ bout,
                                                float* __restrict__ outp){
    extern __shared__ bf16 smem[];
    uint32_t sb = s2u(smem);
    int tid = threadIdx.x, wid = tid >> 5, lid = tid & 31;
    int wm = wid & 3, wn = wid >> 2;
    int h = blockIdx.z;
    int m0 = blockIdx.y * 128, n0 = blockIdx.x * 64;
    const int K   = (MODE==1) ? NDIM : (MODE==2) ? Ln : 256;
    const int nit = K / 32;

    const bf16 *Ah, *Al, *Bh, *Bl; int lda = 0, ldb = 0;
    if (MODE == 0){
        Ah = g_bufA_hi; Al = g_bufA_lo; lda = 256;
        Bh = g_wt_hi;   Bl = g_wt_lo;   ldb = 256;
    } else if (MODE == 1){
        size_t o = (size_t)h * Ln * NDIM;
        Ah = g_bufB_hi + o; Al = g_bufB_lo + o; lda = NDIM;
        Bh = g_k_hi + o;    Bl = g_k_lo + o;    ldb = NDIM;
    } else if (MODE == 2){
        size_t oa = (size_t)h * Ln * Ln;
        Ah = g_p_hi + oa; Al = g_p_lo + oa; lda = Ln;
        size_t ob = (size_t)h * NDIM * Ln;
        Bh = g_bufA_hi + ob; Bl = g_bufA_lo + ob; ldb = Ln;
    } else {
        Ah = g_bufB_hi; Al = g_bufB_lo; lda = 0;
        Bh = g_wt_hi + 1024*256; Bl = g_wt_lo + 1024*256; ldb = 256;
    }

    float acc[2][4][4] = {};

    auto issue = [&](int it){
        int b = it % STAGES, kt = it * 32;
        #pragma unroll
        for (int t = 0; t < 2; t++){
            int q = tid + t*256;
            int r = q >> 2, cc = q & 3;
            uint32_t so = sb + 2*(b*BUFE + r*RS + cc*8);
            const bf16 *gh, *gl;
            if (MODE == 3){
                int row = m0 + r; int n = row >> 9, l = row & (Ln-1);
                int c0 = kt + cc*8; int hh = c0 >> 5, d0 = c0 & 31;
                size_t off = ((size_t)(hh*Ln + l))*NDIM + (n << 5) + d0;
                gh = Ah + off; gl = Al + off;
            } else {
                size_t off = (size_t)(m0 + r)*lda + kt + cc*8;
                gh = Ah + off; gl = Al + off;
            }
            CP16(so, gh);
            CP16(so + 2*AELE, gl);
        }
        {
            int r = tid >> 2, cc = tid & 3;
            uint32_t so = sb + 2*(b*BUFE + 2*AELE + r*RS + cc*8);
            size_t off = (size_t)(n0 + r)*ldb + kt + cc*8;
            CP16(so, Bh + off);
            CP16(so + 2*BELE, Bl + off);
        }
        CPCOMMIT();
    };

    issue(0);
    issue(1);
    for (int it = 0; it < nit; it++){
        if (it < nit - 1) { CPWAIT(1); } else { CPWAIT(0); }
        __syncthreads();
        if (it + 2 < nit) issue(it + 2);
        int b = it % STAGES;
        #pragma unroll
        for (int kk = 0; kk < 2; kk++){
            uint32_t ah[2][4], al[2][4], bh[2][4], bl[2][4];
            int lrow = lid & 15, lch = lid >> 4;
            #pragma unroll
            for (int mi = 0; mi < 2; mi++){
                uint32_t base = sb + 2*(b*BUFE + (wm*32 + mi*16 + lrow)*RS + kk*16 + lch*8);
                ldsm4(base, ah[mi]);
                ldsm4(base + 2*AELE, al[mi]);
            }
            #pragma unroll
            for (int nj = 0; nj < 2; nj++){
                uint32_t base = sb + 2*(b*BUFE + 2*AELE + (wn*32 + nj*16 + lrow)*RS + kk*16 + lch*8);
                ldsm4(base, bh[nj]);
                ldsm4(base + 2*BELE, bl[nj]);
            }
            #pragma unroll
            for (int mi = 0; mi < 2; mi++)
                #pragma unroll
                for (int ni = 0; ni < 4; ni++){
                    int nj = ni >> 1, sel = ni & 1;
                    mma16816(acc[mi][ni], ah[mi], bh[nj][sel], bh[nj][2+sel]);
                    mma16816(acc[mi][ni], ah[mi], bl[nj][sel], bl[nj][2+sel]);
                    mma16816(acc[mi][ni], al[mi], bh[nj][sel], bh[nj][2+sel]);
                }
        }
    }

    // epilogue
    int lr = lid >> 2, lc = (lid & 3)*2;
    #pragma unroll
    for (int mi = 0; mi < 2; mi++){
        #pragma unroll
        for (int ni = 0; ni < 4; ni++){
            #pragma unroll
            for (int e = 0; e < 4; e++){
                int row = m0 + wm*32 + mi*16 + lr + (e >= 2 ? 8 : 0);
                int gcol = n0 + wn*32 + ni*8 + lc + (e & 1);
                float val = acc[mi][ni][e];
                if (MODE == 0){
                    int z = gcol >> 8, j = gcol & 255;
                    int l = row & (Ln-1), n = row >> 9;
                    bool pad = (mask[l] == 0);
                    if (z == 3){
                        g_gate[(size_t)row*HD + j] = 1.f/(1.f + expf(-(val + bg[j])));
                    } else {
                        float v2 = pad ? 0.f : (z == 1 ? val*SCALING : val);
                        int hh = j >> 5, d = j & 31;
                        size_t idx = ((size_t)(hh*Ln + l))*NDIM + (n << 5) + d;
                        if (z == 0)      split_store(g_bufB_hi, g_bufB_lo, idx, v2);
                        else if (z == 1) split_store(g_k_hi, g_k_lo, idx, v2);
                        else             split_store(g_v_hi, g_v_lo, idx, v2);
                    }
                } else if (MODE == 1){
                    g_attn[((size_t)(h*Ln + row))*Ln + gcol] = val;
                } else if (MODE == 2){
                    int n = gcol >> 5, d = gcol & 31;
                    float gt = g_gate[((size_t)(n*Ln + row))*HD + h*32 + d];
                    split_store(g_bufB_hi, g_bufB_lo, ((size_t)(h*Ln + row))*NDIM + gcol, val*gt);
                } else {
                    int l = row & (Ln-1);
                    bool pad = (mask[l] == 0);
                    outp[(size_t)row*HD + gcol] = pad ? 0.f : (val + bout[gcol]);
                }
            }
        }
    }
}

// ----------------------------------------------------------------------------
extern "C" void kernel_launch(void* const* d_in, const int* in_sizes, int n_in,
                              void* d_out, int out_size){
    const float* msa      = (const float*)d_in[0];
    const float* pair     = (const float*)d_in[1];
    const float* ln_msa_g = (const float*)d_in[2];
    const float* ln_msa_b = (const float*)d_in[3];
    const float* ln_pr_g  = (const float*)d_in[4];
    const float* ln_pr_b  = (const float*)d_in[5];
    const float* w_q      = (const float*)d_in[6];
    const float* w_k      = (const float*)d_in[7];
    const float* w_v      = (const float*)d_in[8];
    const float* w_b      = (const float*)d_in[9];
    const float* w_g      = (const float*)d_in[10];
    const float* b_g      = (const float*)d_in[11];
    const float* w_out    = (const float*)d_in[12];
    const float* b_out    = (const float*)d_in[13];
    const int*   mask     = (const int*)  d_in[14];
    float* out = (float*)d_out;

    cudaFuncSetAttribute(k_mma<0>, cudaFuncAttributeMaxDynamicSharedMemorySize, SMEMB);
    cudaFuncSetAttribute(k_mma<1>, cudaFuncAttributeMaxDynamicSharedMemorySize, SMEMB);
    cudaFuncSetAttribute(k_mma<2>, cudaFuncAttributeMaxDynamicSharedMemorySize, SMEMB);
    cudaFuncSetAttribute(k_mma<3>, cudaFuncAttributeMaxDynamicSharedMemorySize, SMEMB);

    k_ln_msa   <<<NL/8, 256>>>(msa, ln_msa_g, ln_msa_b);
    k_conv_w   <<<1280, 256>>>(w_q, w_k, w_v, w_g, w_out);
    k_pair_bias<<<(Ln*Ln)/8, 256>>>(pair, ln_pr_g, ln_pr_b, w_b);
    k_mma<0>   <<<dim3(16, 1024, 1), 256, SMEMB>>>(mask, b_g, b_out, out);
    k_transpose_v<<<dim3(NDIM/32, Ln/32, 16), dim3(32, 8)>>>();
    k_mma<1>   <<<dim3(8, 4, 8),    256, SMEMB>>>(mask, b_g, b_out, out);
    k_softmax  <<<Hh*Ln, 256>>>(mask);
    k_mma<2>   <<<dim3(128, 4, 8),  256, SMEMB>>>(mask, b_g, b_out, out);
    k_mma<3>   <<<dim3(4, 1024, 1), 256, SMEMB>>>(mask, b_g, b_out, out);
}

// round 9
// speedup vs baseline: 1.5766x; 1.5766x over previous
#include <cuda_runtime.h>
#include <cuda_bf16.h>
#include <stdint.h>
#include <math.h>

// Problem dims
#define Ln 512
#define Nn 256
#define DMSA 256
#define DPAIR 128
#define Hh 8
#define Dd 32
#define HD 256
#define NL (Nn*Ln)          // 131072
#define NDIM 8192           // (n,d) contraction dim
#define SCALING 0.17677669529663689f
#define EPSC 1e-5f

typedef __nv_bfloat16 bf16;

// ----------------------------------------------------------------------------
// Scratch (device globals). Aliasing:
//   g_bufA = msa_n (hi/lo)  then  v^T (hi/lo)
//   g_bufB = q (hi/lo)      then  o (hi/lo)
__device__ __align__(16) bf16 g_bufA_hi[33554432];
__device__ __align__(16) bf16 g_bufA_lo[33554432];
__device__ __align__(16) bf16 g_bufB_hi[33554432];
__device__ __align__(16) bf16 g_bufB_lo[33554432];
__device__ __align__(16) bf16 g_k_hi[33554432];   // [h][l][nd]
__device__ __align__(16) bf16 g_k_lo[33554432];
__device__ __align__(16) bf16 g_v_hi[33554432];   // [h][l][nd]
__device__ __align__(16) bf16 g_v_lo[33554432];
__device__ __align__(16) bf16 g_p_hi[2097152];    // [h][q][k]
__device__ __align__(16) bf16 g_p_lo[2097152];
__device__ __align__(16) bf16 g_wt_hi[327680];    // [1280][256]
__device__ __align__(16) bf16 g_wt_lo[327680];
__device__ float g_gate[33554432];                // [r=(n,l)][h*32+d]
__device__ float g_attn[2097152];                 // [h][q][k]
__device__ float g_bias[2097152];                 // [q][k][h]

// ----------------------------------------------------------------------------
__device__ __forceinline__ uint32_t s2u(const void* p){
    uint32_t a;
    asm("{ .reg .u64 t; cvta.to.shared.u64 t, %1; cvt.u32.u64 %0, t; }" : "=r"(a) : "l"(p));
    return a;
}
#define CP16(sa, gp) \
    asm volatile("cp.async.cg.shared.global [%0], [%1], 16;" :: "r"(sa), "l"(gp))
#define CPCOMMIT() asm volatile("cp.async.commit_group;" ::: "memory")
#define CPWAIT(n)  asm volatile("cp.async.wait_group %0;" :: "n"(n) : "memory")

__device__ __forceinline__ void ldsm4(uint32_t a, uint32_t r[4]){
    asm volatile("ldmatrix.sync.aligned.m8n8.x4.shared.b16 {%0,%1,%2,%3}, [%4];"
                 : "=r"(r[0]), "=r"(r[1]), "=r"(r[2]), "=r"(r[3]) : "r"(a));
}
__device__ __forceinline__ void mma16816(float c[4], const uint32_t a[4],
                                         uint32_t b0, uint32_t b1){
    asm volatile("mma.sync.aligned.m16n8k16.row.col.f32.bf16.bf16.f32 "
                 "{%0,%1,%2,%3}, {%4,%5,%6,%7}, {%8,%9}, {%0,%1,%2,%3};"
                 : "+f"(c[0]), "+f"(c[1]), "+f"(c[2]), "+f"(c[3])
                 : "r"(a[0]), "r"(a[1]), "r"(a[2]), "r"(a[3]), "r"(b0), "r"(b1));
}
__device__ __forceinline__ void split_store(bf16* hi, bf16* lo, size_t idx, float v){
    bf16 h = __float2bfloat16(v);
    hi[idx] = h;
    lo[idx] = __float2bfloat16(v - __bfloat162float(h));
}
__device__ __forceinline__ float fixf(float v){
    if (isnan(v)) return 0.f;
    if (isinf(v)) return v > 0.f ? 3.4028234663852886e38f : -3.4028234663852886e38f;
    return v;
}

// ----------------------------------------------------------------------------
// LayerNorm msa -> bufA (bf16 hi/lo)
__global__ void k_ln_msa(const float* __restrict__ msa,
                         const float* __restrict__ g,
                         const float* __restrict__ b){
    int warp = threadIdx.x >> 5, lane = threadIdx.x & 31;
    size_t row = (size_t)blockIdx.x * 8 + warp;
    const float* x = msa + row * DMSA;
    float v[8]; float s = 0.f;
    #pragma unroll
    for (int i = 0; i < 8; i++){ float t = fixf(x[lane + i*32]); v[i] = t; s += t; }
    #pragma unroll
    for (int o = 16; o; o >>= 1) s += __shfl_xor_sync(0xffffffffu, s, o);
    float mu = s * (1.f/256.f);
    float q = 0.f;
    #pragma unroll
    for (int i = 0; i < 8; i++){ float d0 = v[i] - mu; q += d0*d0; }
    #pragma unroll
    for (int o = 16; o; o >>= 1) q += __shfl_xor_sync(0xffffffffu, q, o);
    float rs = rsqrtf(q * (1.f/256.f) + EPSC);
    #pragma unroll
    for (int i = 0; i < 8; i++){
        int c = lane + i*32;
        float y = (v[i] - mu) * rs * g[c] + b[c];
        split_store(g_bufA_hi, g_bufA_lo, row*DMSA + c, y);
    }
}

// Weight transpose+split: g_wt[row=(z*256+j)][k] = W_z[k][j]
__global__ void k_conv_w(const float* __restrict__ wq, const float* __restrict__ wk,
                         const float* __restrict__ wv, const float* __restrict__ wg,
                         const float* __restrict__ wo){
    int row = blockIdx.x, kk = threadIdx.x;
    int z = row >> 8, j = row & 255;
    const float* src = (z==0)?wq:(z==1)?wk:(z==2)?wv:(z==3)?wg:wo;
    float v = src[kk*256 + j];
    split_store(g_wt_hi, g_wt_lo, (size_t)row*256 + kk, v);
}

// LayerNorm pair + bias GEMV
__global__ void k_pair_bias(const float* __restrict__ pair,
                            const float* __restrict__ g,
                            const float* __restrict__ b,
                            const float* __restrict__ wb){
    __shared__ float swb[Hh*DPAIR];
    for (int i = threadIdx.x; i < Hh*DPAIR; i += blockDim.x){
        int h = i / DPAIR, c = i % DPAIR;
        swb[i] = wb[c*Hh + h];
    }
    __syncthreads();
    int warp = threadIdx.x >> 5, lane = threadIdx.x & 31;
    size_t row = (size_t)blockIdx.x * 8 + warp;
    const float* x = pair + row * DPAIR;
    float v[4]; float s = 0.f;
    #pragma unroll
    for (int i = 0; i < 4; i++){ float t = fixf(x[lane + i*32]); v[i] = t; s += t; }
    #pragma unroll
    for (int o = 16; o; o >>= 1) s += __shfl_xor_sync(0xffffffffu, s, o);
    float mu = s * (1.f/128.f);
    float q = 0.f;
    #pragma unroll
    for (int i = 0; i < 4; i++){ float d0 = v[i] - mu; q += d0*d0; }
    #pragma unroll
    for (int o = 16; o; o >>= 1) q += __shfl_xor_sync(0xffffffffu, q, o);
    float rs = rsqrtf(q * (1.f/128.f) + EPSC);
    float acc[8] = {};
    #pragma unroll
    for (int i = 0; i < 4; i++){
        int c = lane + i*32;
        float pn = (v[i] - mu) * rs * g[c] + b[c];
        #pragma unroll
        for (int h = 0; h < 8; h++) acc[h] += pn * swb[h*DPAIR + c];
    }
    #pragma unroll
    for (int h = 0; h < 8; h++)
        #pragma unroll
        for (int o = 16; o; o >>= 1) acc[h] += __shfl_xor_sync(0xffffffffu, acc[h], o);
    float outv = 0.f;
    #pragma unroll
    for (int h = 0; h < 8; h++) if (lane == h) outv = acc[h];
    if (lane < 8) g_bias[row*Hh + lane] = outv;
}

// Transpose V: [h][l][nd] -> [h][nd][l] into bufA
__global__ void k_transpose_v(){
    __shared__ bf16 tile[32][33];
    int head = blockIdx.z >> 1, arr = blockIdx.z & 1;
    const bf16* src = (arr ? g_v_lo : g_v_hi) + (size_t)head * Ln * NDIM;
    bf16* dst = (arr ? g_bufA_lo : g_bufA_hi) + (size_t)head * NDIM * Ln;
    int nd0 = blockIdx.x * 32, l0 = blockIdx.y * 32;
    #pragma unroll
    for (int yy = 0; yy < 4; yy++)
        tile[threadIdx.y + yy*8][threadIdx.x] =
            src[(size_t)(l0 + threadIdx.y + yy*8) * NDIM + nd0 + threadIdx.x];
    __syncthreads();
    #pragma unroll
    for (int yy = 0; yy < 4; yy++)
        dst[(size_t)(nd0 + threadIdx.y + yy*8) * Ln + l0 + threadIdx.x] =
            tile[threadIdx.x][threadIdx.y + yy*8];
}

// Softmax over k with bias + mask; writes P as bf16 hi/lo
__global__ void k_softmax(const int* __restrict__ mask){
    int h = blockIdx.x >> 9, q = blockIdx.x & (Ln-1);
    const float* row = g_attn + ((size_t)h*Ln + q)*Ln;
    bool padq = (mask[q] == 0);
    int t = threadIdx.x;
    int k0 = t, k1 = t + 256;
    float v0 = (padq || mask[k0] == 0) ? -1e9f : row[k0] + g_bias[((size_t)q*Ln + k0)*Hh + h];
    float v1 = (padq || mask[k1] == 0) ? -1e9f : row[k1] + g_bias[((size_t)q*Ln + k1)*Hh + h];
    __shared__ float red[256];
    red[t] = fmaxf(v0, v1); __syncthreads();
    for (int s = 128; s > 0; s >>= 1){ if (t < s) red[t] = fmaxf(red[t], red[t+s]); __syncthreads(); }
    float m = red[0]; __syncthreads();
    float e0 = expf(v0 - m), e1 = expf(v1 - m);
    red[t] = e0 + e1; __syncthreads();
    for (int s = 128; s > 0; s >>= 1){ if (t < s) red[t] += red[t+s]; __syncthreads(); }
    float inv = 1.f / red[0];
    size_t base = ((size_t)h*Ln + q)*Ln;
    split_store(g_p_hi, g_p_lo, base + k0, e0*inv);
    split_store(g_p_hi, g_p_lo, base + k1, e1*inv);
}

// ----------------------------------------------------------------------------
// Warp-MMA GEMM. MODE: 0=QKVG, 1=attn logits, 2=AV, 3=out-proj
// D[BM=128, BN=64] = A[M,K] @ B[N,K]^T,  A/B bf16 hi/lo K-major.
// 8 warps: 4(M) x 2(N), each 32x32.  BK=32, double-buffered cp.async.
// 3 CTAs/SM (occupancy lever; regs capped at 85 by launch bounds).
// SMEM row stride: 40 bf16 (80 B, 16B-aligned rows; i*20 words mod 32 distinct
// over 8 rows -> conflict-free ldmatrix).
#define RS   40
#define AELE 5120             // 128*40
#define BELE 2560             // 64*40
#define BUFE 15360            // Ah+Al+Bh+Bl elems per buffer
#define SMEMB (2*BUFE*2)      // 61440 bytes

template<int MODE>
__global__ __launch_bounds__(256, 3) void k_mma(const int* __restrict__ mask,
                                                const float* __restrict__ bg,
                                                const float* __restrict__ bout,
                                                float* __restrict__ outp){
    extern __shared__ bf16 smem[];
    uint32_t sb = s2u(smem);
    int tid = threadIdx.x, wid = tid >> 5, lid = tid & 31;
    int wm = wid & 3, wn = wid >> 2;
    int h = blockIdx.z;
    int m0 = blockIdx.y * 128, n0 = blockIdx.x * 64;
    const int K   = (MODE==1) ? NDIM : (MODE==2) ? Ln : 256;
    const int nit = K / 32;

    const bf16 *Ah, *Al, *Bh, *Bl; int lda = 0, ldb = 0;
    if (MODE == 0){
        Ah = g_bufA_hi; Al = g_bufA_lo; lda = 256;
        Bh = g_wt_hi;   Bl = g_wt_lo;   ldb = 256;
    } else if (MODE == 1){
        size_t o = (size_t)h * Ln * NDIM;
        Ah = g_bufB_hi + o; Al = g_bufB_lo + o; lda = NDIM;
        Bh = g_k_hi + o;    Bl = g_k_lo + o;    ldb = NDIM;
    } else if (MODE == 2){
        size_t oa = (size_t)h * Ln * Ln;
        Ah = g_p_hi + oa; Al = g_p_lo + oa; lda = Ln;
        size_t ob = (size_t)h * NDIM * Ln;
        Bh = g_bufA_hi + ob; Bl = g_bufA_lo + ob; ldb = Ln;
    } else {
        Ah = g_bufB_hi; Al = g_bufB_lo; lda = 0;
        Bh = g_wt_hi + 1024*256; Bl = g_wt_lo + 1024*256; ldb = 256;
    }

    float acc[2][4][4] = {};

    auto issue = [&](int it){
        int b = it & 1, kt = it * 32;
        #pragma unroll
        for (int t = 0; t < 2; t++){
            int q = tid + t*256;
            int r = q >> 2, cc = q & 3;
            uint32_t so = sb + 2*(b*BUFE + r*RS + cc*8);
            const bf16 *gh, *gl;
            if (MODE == 3){
                int row = m0 + r; int n = row >> 9, l = row & (Ln-1);
                int c0 = kt + cc*8; int hh = c0 >> 5, d0 = c0 & 31;
                size_t off = ((size_t)(hh*Ln + l))*NDIM + (n << 5) + d0;
                gh = Ah + off; gl = Al + off;
            } else {
                size_t off = (size_t)(m0 + r)*lda + kt + cc*8;
                gh = Ah + off; gl = Al + off;
            }
            CP16(so, gh);
            CP16(so + 2*AELE, gl);
        }
        {
            int r = tid >> 2, cc = tid & 3;
            uint32_t so = sb + 2*(b*BUFE + 2*AELE + r*RS + cc*8);
            size_t off = (size_t)(n0 + r)*ldb + kt + cc*8;
            CP16(so, Bh + off);
            CP16(so + 2*BELE, Bl + off);
        }
        CPCOMMIT();
    };

    issue(0);
    for (int it = 0; it < nit; it++){
        if (it + 1 < nit){ issue(it + 1); CPWAIT(1); }
        else             { CPWAIT(0); }
        __syncthreads();
        int b = it & 1;
        #pragma unroll
        for (int kk = 0; kk < 2; kk++){
            uint32_t ah[2][4], al[2][4], bh[2][4], bl[2][4];
            int lrow = lid & 15, lch = lid >> 4;
            #pragma unroll
            for (int mi = 0; mi < 2; mi++){
                uint32_t base = sb + 2*(b*BUFE + (wm*32 + mi*16 + lrow)*RS + kk*16 + lch*8);
                ldsm4(base, ah[mi]);
                ldsm4(base + 2*AELE, al[mi]);
            }
            #pragma unroll
            for (int nj = 0; nj < 2; nj++){
                uint32_t base = sb + 2*(b*BUFE + 2*AELE + (wn*32 + nj*16 + lrow)*RS + kk*16 + lch*8);
                ldsm4(base, bh[nj]);
                ldsm4(base + 2*BELE, bl[nj]);
            }
            #pragma unroll
            for (int mi = 0; mi < 2; mi++)
                #pragma unroll
                for (int ni = 0; ni < 4; ni++){
                    int nj = ni >> 1, sel = ni & 1;
                    mma16816(acc[mi][ni], ah[mi], bh[nj][sel], bh[nj][2+sel]);
                    mma16816(acc[mi][ni], ah[mi], bl[nj][sel], bl[nj][2+sel]);
                    mma16816(acc[mi][ni], al[mi], bh[nj][sel], bh[nj][2+sel]);
                }
        }
        __syncthreads();
    }

    // epilogue
    int lr = lid >> 2, lc = (lid & 3)*2;
    #pragma unroll
    for (int mi = 0; mi < 2; mi++){
        #pragma unroll
        for (int ni = 0; ni < 4; ni++){
            #pragma unroll
            for (int e = 0; e < 4; e++){
                int row = m0 + wm*32 + mi*16 + lr + (e >= 2 ? 8 : 0);
                int gcol = n0 + wn*32 + ni*8 + lc + (e & 1);
                float val = acc[mi][ni][e];
                if (MODE == 0){
                    int z = gcol >> 8, j = gcol & 255;
                    int l = row & (Ln-1), n = row >> 9;
                    bool pad = (mask[l] == 0);
                    if (z == 3){
                        g_gate[(size_t)row*HD + j] = 1.f/(1.f + expf(-(val + bg[j])));
                    } else {
                        float v2 = pad ? 0.f : (z == 1 ? val*SCALING : val);
                        int hh = j >> 5, d = j & 31;
                        size_t idx = ((size_t)(hh*Ln + l))*NDIM + (n << 5) + d;
                        if (z == 0)      split_store(g_bufB_hi, g_bufB_lo, idx, v2);
                        else if (z == 1) split_store(g_k_hi, g_k_lo, idx, v2);
                        else             split_store(g_v_hi, g_v_lo, idx, v2);
                    }
                } else if (MODE == 1){
                    g_attn[((size_t)(h*Ln + row))*Ln + gcol] = val;
                } else if (MODE == 2){
                    int n = gcol >> 5, d = gcol & 31;
                    float gt = g_gate[((size_t)(n*Ln + row))*HD + h*32 + d];
                    split_store(g_bufB_hi, g_bufB_lo, ((size_t)(h*Ln + row))*NDIM + gcol, val*gt);
                } else {
                    int l = row & (Ln-1);
                    bool pad = (mask[l] == 0);
                    outp[(size_t)row*HD + gcol] = pad ? 0.f : (val + bout[gcol]);
                }
            }
        }
    }
}

// ----------------------------------------------------------------------------
extern "C" void kernel_launch(void* const* d_in, const int* in_sizes, int n_in,
                              void* d_out, int out_size){
    const float* msa      = (const float*)d_in[0];
    const float* pair     = (const float*)d_in[1];
    const float* ln_msa_g = (const float*)d_in[2];
    const float* ln_msa_b = (const float*)d_in[3];
    const float* ln_pr_g  = (const float*)d_in[4];
    const float* ln_pr_b  = (const float*)d_in[5];
    const float* w_q      = (const float*)d_in[6];
    const float* w_k      = (const float*)d_in[7];
    const float* w_v      = (const float*)d_in[8];
    const float* w_b      = (const float*)d_in[9];
    const float* w_g      = (const float*)d_in[10];
    const float* b_g      = (const float*)d_in[11];
    const float* w_out    = (const float*)d_in[12];
    const float* b_out    = (const float*)d_in[13];
    const int*   mask     = (const int*)  d_in[14];
    float* out = (float*)d_out;

    cudaFuncSetAttribute(k_mma<0>, cudaFuncAttributeMaxDynamicSharedMemorySize, SMEMB);
    cudaFuncSetAttribute(k_mma<1>, cudaFuncAttributeMaxDynamicSharedMemorySize, SMEMB);
    cudaFuncSetAttribute(k_mma<2>, cudaFuncAttributeMaxDynamicSharedMemorySize, SMEMB);
    cudaFuncSetAttribute(k_mma<3>, cudaFuncAttributeMaxDynamicSharedMemorySize, SMEMB);

    k_ln_msa   <<<NL/8, 256>>>(msa, ln_msa_g, ln_msa_b);
    k_conv_w   <<<1280, 256>>>(w_q, w_k, w_v, w_g, w_out);
    k_pair_bias<<<(Ln*Ln)/8, 256>>>(pair, ln_pr_g, ln_pr_b, w_b);
    k_mma<0>   <<<dim3(16, 1024, 1), 256, SMEMB>>>(mask, b_g, b_out, out);
    k_transpose_v<<<dim3(NDIM/32, Ln/32, 16), dim3(32, 8)>>>();
    k_mma<1>   <<<dim3(8, 4, 8),    256, SMEMB>>>(mask, b_g, b_out, out);
    k_softmax  <<<Hh*Ln, 256>>>(mask);
    k_mma<2>   <<<dim3(128, 4, 8),  256, SMEMB>>>(mask, b_g, b_out, out);
    k_mma<3>   <<<dim3(4, 1024, 1), 256, SMEMB>>>(mask, b_g, b_out, out);
}

// round 11
// speedup vs baseline: 3.0360x; 1.9257x over previous
#include <cuda_runtime.h>
#include <cuda_fp16.h>
#include <stdint.h>
#include <math.h>

// Problem dims
#define Ln 512
#define Nn 256
#define DMSA 256
#define DPAIR 128
#define Hh 8
#define Dd 32
#define HD 256
#define NL (Nn*Ln)          // 131072
#define NDIM 8192           // (n,d) contraction dim
#define SCALING 0.17677669529663689f
#define EPSC 1e-5f

typedef __half hf;

// ----------------------------------------------------------------------------
// Scratch (device globals). Aliasing:
//   g_bufA = msa_n  then  v^T     g_bufB = q  then  o
__device__ __align__(16) hf g_bufA[33554432];
__device__ __align__(16) hf g_bufB[33554432];
__device__ __align__(16) hf g_k[33554432];     // [h][l][nd]
__device__ __align__(16) hf g_v[33554432];     // [h][l][nd]
__device__ __align__(16) hf g_p[2097152];      // [h][q][k]
__device__ __align__(16) hf g_wt[327680];      // [1280][256]: 0..1023 wq|wk|wv|wg ^T, 1024..1279 w_out^T
__device__ float g_gate[33554432];             // [r=(n,l)][h*32+d]
__device__ float g_attn[2097152];              // [h][q][k]
__device__ float g_bias[2097152];              // [q][k][h]

// ----------------------------------------------------------------------------
__device__ __forceinline__ uint32_t s2u(const void* p){
    uint32_t a;
    asm("{ .reg .u64 t; cvta.to.shared.u64 t, %1; cvt.u32.u64 %0, t; }" : "=r"(a) : "l"(p));
    return a;
}
#define CP16(sa, gp) \
    asm volatile("cp.async.cg.shared.global [%0], [%1], 16;" :: "r"(sa), "l"(gp))
#define CPCOMMIT() asm volatile("cp.async.commit_group;" ::: "memory")
#define CPWAIT(n)  asm volatile("cp.async.wait_group %0;" :: "n"(n) : "memory")

__device__ __forceinline__ void ldsm4(uint32_t a, uint32_t r[4]){
    asm volatile("ldmatrix.sync.aligned.m8n8.x4.shared.b16 {%0,%1,%2,%3}, [%4];"
                 : "=r"(r[0]), "=r"(r[1]), "=r"(r[2]), "=r"(r[3]) : "r"(a));
}
__device__ __forceinline__ void mma16816(float c[4], const uint32_t a[4],
                                         uint32_t b0, uint32_t b1){
    asm volatile("mma.sync.aligned.m16n8k16.row.col.f32.f16.f16.f32 "
                 "{%0,%1,%2,%3}, {%4,%5,%6,%7}, {%8,%9}, {%0,%1,%2,%3};"
                 : "+f"(c[0]), "+f"(c[1]), "+f"(c[2]), "+f"(c[3])
                 : "r"(a[0]), "r"(a[1]), "r"(a[2]), "r"(a[3]), "r"(b0), "r"(b1));
}
__device__ __forceinline__ float fixf(float v){
    if (isnan(v)) return 0.f;
    if (isinf(v)) return v > 0.f ? 3.4028234663852886e38f : -3.4028234663852886e38f;
    return v;
}

// ----------------------------------------------------------------------------
// LayerNorm msa -> bufA (fp16)
__global__ void k_ln_msa(const float* __restrict__ msa,
                         const float* __restrict__ g,
                         const float* __restrict__ b){
    int warp = threadIdx.x >> 5, lane = threadIdx.x & 31;
    size_t row = (size_t)blockIdx.x * 8 + warp;
    const float* x = msa + row * DMSA;
    float v[8]; float s = 0.f;
    #pragma unroll
    for (int i = 0; i < 8; i++){ float t = fixf(x[lane + i*32]); v[i] = t; s += t; }
    #pragma unroll
    for (int o = 16; o; o >>= 1) s += __shfl_xor_sync(0xffffffffu, s, o);
    float mu = s * (1.f/256.f);
    float q = 0.f;
    #pragma unroll
    for (int i = 0; i < 8; i++){ float d0 = v[i] - mu; q += d0*d0; }
    #pragma unroll
    for (int o = 16; o; o >>= 1) q += __shfl_xor_sync(0xffffffffu, q, o);
    float rs = rsqrtf(q * (1.f/256.f) + EPSC);
    #pragma unroll
    for (int i = 0; i < 8; i++){
        int c = lane + i*32;
        g_bufA[row*DMSA + c] = __float2half_rn((v[i] - mu) * rs * g[c] + b[c]);
    }
}

// Weight transpose: g_wt[row=(z*256+j)][k] = W_z[k][j]
__global__ void k_conv_w(const float* __restrict__ wq, const float* __restrict__ wk,
                         const float* __restrict__ wv, const float* __restrict__ wg,
                         const float* __restrict__ wo){
    int row = blockIdx.x, kk = threadIdx.x;
    int z = row >> 8, j = row & 255;
    const float* src = (z==0)?wq:(z==1)?wk:(z==2)?wv:(z==3)?wg:wo;
    g_wt[(size_t)row*256 + kk] = __float2half_rn(src[kk*256 + j]);
}

// LayerNorm pair + bias GEMV
__global__ void k_pair_bias(const float* __restrict__ pair,
                            const float* __restrict__ g,
                            const float* __restrict__ b,
                            const float* __restrict__ wb){
    __shared__ float swb[Hh*DPAIR];
    for (int i = threadIdx.x; i < Hh*DPAIR; i += blockDim.x){
        int h = i / DPAIR, c = i % DPAIR;
        swb[i] = wb[c*Hh + h];
    }
    __syncthreads();
    int warp = threadIdx.x >> 5, lane = threadIdx.x & 31;
    size_t row = (size_t)blockIdx.x * 8 + warp;
    const float* x = pair + row * DPAIR;
    float v[4]; float s = 0.f;
    #pragma unroll
    for (int i = 0; i < 4; i++){ float t = fixf(x[lane + i*32]); v[i] = t; s += t; }
    #pragma unroll
    for (int o = 16; o; o >>= 1) s += __shfl_xor_sync(0xffffffffu, s, o);
    float mu = s * (1.f/128.f);
    float q = 0.f;
    #pragma unroll
    for (int i = 0; i < 4; i++){ float d0 = v[i] - mu; q += d0*d0; }
    #pragma unroll
    for (int o = 16; o; o >>= 1) q += __shfl_xor_sync(0xffffffffu, q, o);
    float rs = rsqrtf(q * (1.f/128.f) + EPSC);
    float acc[8] = {};
    #pragma unroll
    for (int i = 0; i < 4; i++){
        int c = lane + i*32;
        float pn = (v[i] - mu) * rs * g[c] + b[c];
        #pragma unroll
        for (int h = 0; h < 8; h++) acc[h] += pn * swb[h*DPAIR + c];
    }
    #pragma unroll
    for (int h = 0; h < 8; h++)
        #pragma unroll
        for (int o = 16; o; o >>= 1) acc[h] += __shfl_xor_sync(0xffffffffu, acc[h], o);
    float outv = 0.f;
    #pragma unroll
    for (int h = 0; h < 8; h++) if (lane == h) outv = acc[h];
    if (lane < 8) g_bias[row*Hh + lane] = outv;
}

// Transpose V: [h][l][nd] -> [h][nd][l] into bufA
__global__ void k_transpose_v(){
    __shared__ hf tile[32][33];
    int head = blockIdx.z;
    const hf* src = g_v + (size_t)head * Ln * NDIM;
    hf* dst = g_bufA + (size_t)head * NDIM * Ln;
    int nd0 = blockIdx.x * 32, l0 = blockIdx.y * 32;
    #pragma unroll
    for (int yy = 0; yy < 4; yy++)
        tile[threadIdx.y + yy*8][threadIdx.x] =
            src[(size_t)(l0 + threadIdx.y + yy*8) * NDIM + nd0 + threadIdx.x];
    __syncthreads();
    #pragma unroll
    for (int yy = 0; yy < 4; yy++)
        dst[(size_t)(nd0 + threadIdx.y + yy*8) * Ln + l0 + threadIdx.x] =
            tile[threadIdx.x][threadIdx.y + yy*8];
}

// Softmax over k with bias + mask; writes P as fp16
__global__ void k_softmax(const int* __restrict__ mask){
    int h = blockIdx.x >> 9, q = blockIdx.x & (Ln-1);
    const float* row = g_attn + ((size_t)h*Ln + q)*Ln;
    bool padq = (mask[q] == 0);
    int t = threadIdx.x;
    int k0 = t, k1 = t + 256;
    float v0 = (padq || mask[k0] == 0) ? -1e9f : row[k0] + g_bias[((size_t)q*Ln + k0)*Hh + h];
    float v1 = (padq || mask[k1] == 0) ? -1e9f : row[k1] + g_bias[((size_t)q*Ln + k1)*Hh + h];
    __shared__ float red[256];
    red[t] = fmaxf(v0, v1); __syncthreads();
    for (int s = 128; s > 0; s >>= 1){ if (t < s) red[t] = fmaxf(red[t], red[t+s]); __syncthreads(); }
    float m = red[0]; __syncthreads();
    float e0 = expf(v0 - m), e1 = expf(v1 - m);
    red[t] = e0 + e1; __syncthreads();
    for (int s = 128; s > 0; s >>= 1){ if (t < s) red[t] += red[t+s]; __syncthreads(); }
    float inv = 1.f / red[0];
    size_t base = ((size_t)h*Ln + q)*Ln;
    g_p[base + k0] = __float2half_rn(e0*inv);
    g_p[base + k1] = __float2half_rn(e1*inv);
}

// ----------------------------------------------------------------------------
// Warp-MMA GEMM. MODE: 0=QKVG, 1=attn logits, 2=AV, 3=out-proj
// D[BM=128, BN=64] = A[M,K] @ B[N,K]^T, fp16 K-major operands, fp32 accum.
// 8 warps: 4(M) x 2(N), each 32x32.  BK=32, double-buffered cp.async.
// SMEM row stride 40 halves (80B, 16B-aligned; conflict-free ldmatrix).
#define RS   40
#define AELE 5120             // 128*40
#define BELE 2560             // 64*40
#define BUFE 7680             // A+B elems per buffer
#define SMEMB (2*BUFE*2)      // 30720 bytes

template<int MODE>
__global__ __launch_bounds__(256, 4) void k_mma(const int* __restrict__ mask,
                                                const float* __restrict__ bg,
                                                const float* __restrict__ bout,
                                                float* __restrict__ outp){
    extern __shared__ hf smem[];
    uint32_t sb = s2u(smem);
    int tid = threadIdx.x, wid = tid >> 5, lid = tid & 31;
    int wm = wid & 3, wn = wid >> 2;
    int h = blockIdx.z;
    int m0 = blockIdx.y * 128, n0 = blockIdx.x * 64;
    const int K   = (MODE==1) ? NDIM : (MODE==2) ? Ln : 256;
    const int nit = K / 32;

    const hf *A, *B; int lda = 0, ldb = 0;
    if (MODE == 0){
        A = g_bufA; lda = 256;
        B = g_wt;   ldb = 256;
    } else if (MODE == 1){
        size_t o = (size_t)h * Ln * NDIM;
        A = g_bufB + o; lda = NDIM;
        B = g_k + o;    ldb = NDIM;
    } else if (MODE == 2){
        A = g_p + (size_t)h * Ln * Ln; lda = Ln;
        B = g_bufA + (size_t)h * NDIM * Ln; ldb = Ln;
    } else {
        A = g_bufB; lda = 0;
        B = g_wt + 1024*256; ldb = 256;
    }

    float acc[2][4][4] = {};

    auto issue = [&](int it){
        int b = it & 1, kt = it * 32;
        #pragma unroll
        for (int t = 0; t < 2; t++){
            int q = tid + t*256;
            int r = q >> 2, cc = q & 3;
            uint32_t so = sb + 2*(b*BUFE + r*RS + cc*8);
            const hf* gp;
            if (MODE == 3){
                int row = m0 + r; int n = row >> 9, l = row & (Ln-1);
                int c0 = kt + cc*8; int hh = c0 >> 5, d0 = c0 & 31;
                gp = A + ((size_t)(hh*Ln + l))*NDIM + (n << 5) + d0;
            } else {
                gp = A + (size_t)(m0 + r)*lda + kt + cc*8;
            }
            CP16(so, gp);
        }
        {
            int r = tid >> 2, cc = tid & 3;
            uint32_t so = sb + 2*(b*BUFE + AELE + r*RS + cc*8);
            CP16(so, B + (size_t)(n0 + r)*ldb + kt + cc*8);
        }
        CPCOMMIT();
    };

    issue(0);
    for (int it = 0; it < nit; it++){
        if (it + 1 < nit){ issue(it + 1); CPWAIT(1); }
        else             { CPWAIT(0); }
        __syncthreads();
        int b = it & 1;
        #pragma unroll
        for (int kk = 0; kk < 2; kk++){
            uint32_t ah[2][4], bh[2][4];
            int lrow = lid & 15, lch = lid >> 4;
            #pragma unroll
            for (int mi = 0; mi < 2; mi++){
                uint32_t base = sb + 2*(b*BUFE + (wm*32 + mi*16 + lrow)*RS + kk*16 + lch*8);
                ldsm4(base, ah[mi]);
            }
            #pragma unroll
            for (int nj = 0; nj < 2; nj++){
                uint32_t base = sb + 2*(b*BUFE + AELE + (wn*32 + nj*16 + lrow)*RS + kk*16 + lch*8);
                ldsm4(base, bh[nj]);
            }
            #pragma unroll
            for (int mi = 0; mi < 2; mi++)
                #pragma unroll
                for (int ni = 0; ni < 4; ni++){
                    int nj = ni >> 1, sel = ni & 1;
                    mma16816(acc[mi][ni], ah[mi], bh[nj][sel], bh[nj][2+sel]);
                }
        }
        __syncthreads();
    }

    // epilogue
    int lr = lid >> 2, lc = (lid & 3)*2;
    #pragma unroll
    for (int mi = 0; mi < 2; mi++){
        #pragma unroll
        for (int ni = 0; ni < 4; ni++){
            #pragma unroll
            for (int e = 0; e < 4; e++){
                int row = m0 + wm*32 + mi*16 + lr + (e >= 2 ? 8 : 0);
                int gcol = n0 + wn*32 + ni*8 + lc + (e & 1);
                float val = acc[mi][ni][e];
                if (MODE == 0){
                    int z = gcol >> 8, j = gcol & 255;
                    int l = row & (Ln-1), n = row >> 9;
                    bool pad = (mask[l] == 0);
                    if (z == 3){
                        g_gate[(size_t)row*HD + j] = 1.f/(1.f + expf(-(val + bg[j])));
                    } else {
                        float v2 = pad ? 0.f : (z == 1 ? val*SCALING : val);
                        int hh = j >> 5, d = j & 31;
                        size_t idx = ((size_t)(hh*Ln + l))*NDIM + (n << 5) + d;
                        hf hv = __float2half_rn(v2);
                        if (z == 0)      g_bufB[idx] = hv;
                        else if (z == 1) g_k[idx] = hv;
                        else             g_v[idx] = hv;
                    }
                } else if (MODE == 1){
                    g_attn[((size_t)(h*Ln + row))*Ln + gcol] = val;
                } else if (MODE == 2){
                    int n = gcol >> 5, d = gcol & 31;
                    float gt = g_gate[((size_t)(n*Ln + row))*HD + h*32 + d];
                    g_bufB[((size_t)(h*Ln + row))*NDIM + gcol] = __float2half_rn(val*gt);
                } else {
                    int l = row & (Ln-1);
                    bool pad = (mask[l] == 0);
                    outp[(size_t)row*HD + gcol] = pad ? 0.f : (val + bout[gcol]);
                }
            }
        }
    }
}

// ----------------------------------------------------------------------------
extern "C" void kernel_launch(void* const* d_in, const int* in_sizes, int n_in,
                              void* d_out, int out_size){
    const float* msa      = (const float*)d_in[0];
    const float* pair     = (const float*)d_in[1];
    const float* ln_msa_g = (const float*)d_in[2];
    const float* ln_msa_b = (const float*)d_in[3];
    const float* ln_pr_g  = (const float*)d_in[4];
    const float* ln_pr_b  = (const float*)d_in[5];
    const float* w_q      = (const float*)d_in[6];
    const float* w_k      = (const float*)d_in[7];
    const float* w_v      = (const float*)d_in[8];
    const float* w_b      = (const float*)d_in[9];
    const float* w_g      = (const float*)d_in[10];
    const float* b_g      = (const float*)d_in[11];
    const float* w_out    = (const float*)d_in[12];
    const float* b_out    = (const float*)d_in[13];
    const int*   mask     = (const int*)  d_in[14];
    float* out = (float*)d_out;

    cudaFuncSetAttribute(k_mma<0>, cudaFuncAttributeMaxDynamicSharedMemorySize, SMEMB);
    cudaFuncSetAttribute(k_mma<1>, cudaFuncAttributeMaxDynamicSharedMemorySize, SMEMB);
    cudaFuncSetAttribute(k_mma<2>, cudaFuncAttributeMaxDynamicSharedMemorySize, SMEMB);
    cudaFuncSetAttribute(k_mma<3>, cudaFuncAttributeMaxDynamicSharedMemorySize, SMEMB);

    k_ln_msa   <<<NL/8, 256>>>(msa, ln_msa_g, ln_msa_b);
    k_conv_w   <<<1280, 256>>>(w_q, w_k, w_v, w_g, w_out);
    k_pair_bias<<<(Ln*Ln)/8, 256>>>(pair, ln_pr_g, ln_pr_b, w_b);
    k_mma<0>   <<<dim3(16, 1024, 1), 256, SMEMB>>>(mask, b_g, b_out, out);
    k_transpose_v<<<dim3(NDIM/32, Ln/32, 8), dim3(32, 8)>>>();
    k_mma<1>   <<<dim3(8, 4, 8),    256, SMEMB>>>(mask, b_g, b_out, out);
    k_softmax  <<<Hh*Ln, 256>>>(mask);
    k_mma<2>   <<<dim3(128, 4, 8),  256, SMEMB>>>(mask, b_g, b_out, out);
    k_mma<3>   <<<dim3(4, 1024, 1), 256, SMEMB>>>(mask, b_g, b_out, out);
}

// round 15
// speedup vs baseline: 3.6888x; 1.2150x over previous
#include <cuda_runtime.h>
#include <cuda_fp16.h>
#include <stdint.h>
#include <math.h>

// Problem dims
#define Ln 512
#define Nn 256
#define DMSA 256
#define DPAIR 128
#define Hh 8
#define Dd 32
#define HD 256
#define NL (Nn*Ln)          // 131072
#define NDIM 8192           // (n,d) contraction dim
#define SCALING 0.17677669529663689f
#define EPSC 1e-5f

typedef __half hf;

// ----------------------------------------------------------------------------
// Scratch (device globals). Aliasing:
//   g_bufA = msa_n  then  v^T     g_bufB = q  then  o
__device__ __align__(16) hf g_bufA[33554432];
__device__ __align__(16) hf g_bufB[33554432];
__device__ __align__(16) hf g_k[33554432];     // [h][l][nd]
__device__ __align__(16) hf g_v[33554432];     // [h][l][nd]
__device__ __align__(16) hf g_p[2097152];      // [h][q][k]
__device__ __align__(16) hf g_wt[327680];      // [1280][256]: 0..1023 wq|wk|wv|wg ^T, 1024..1279 w_out^T
__device__ float g_gate[33554432];             // [r=(n,l)][h*32+d]
__device__ float g_attn[2097152];              // [h][q][k]
__device__ float g_bias[2097152];              // [q][k][h]

// ----------------------------------------------------------------------------
__device__ __forceinline__ uint32_t s2u(const void* p){
    uint32_t a;
    asm("{ .reg .u64 t; cvta.to.shared.u64 t, %1; cvt.u32.u64 %0, t; }" : "=r"(a) : "l"(p));
    return a;
}
#define CP16(sa, gp) \
    asm volatile("cp.async.cg.shared.global [%0], [%1], 16;" :: "r"(sa), "l"(gp))
#define CPCOMMIT() asm volatile("cp.async.commit_group;" ::: "memory")
#define CPWAIT(n)  asm volatile("cp.async.wait_group %0;" :: "n"(n) : "memory")

__device__ __forceinline__ void ldsm4(uint32_t a, uint32_t r[4]){
    asm volatile("ldmatrix.sync.aligned.m8n8.x4.shared.b16 {%0,%1,%2,%3}, [%4];"
                 : "=r"(r[0]), "=r"(r[1]), "=r"(r[2]), "=r"(r[3]) : "r"(a));
}
__device__ __forceinline__ void mma16816(float c[4], const uint32_t a[4],
                                         uint32_t b0, uint32_t b1){
    asm volatile("mma.sync.aligned.m16n8k16.row.col.f32.f16.f16.f32 "
                 "{%0,%1,%2,%3}, {%4,%5,%6,%7}, {%8,%9}, {%0,%1,%2,%3};"
                 : "+f"(c[0]), "+f"(c[1]), "+f"(c[2]), "+f"(c[3])
                 : "r"(a[0]), "r"(a[1]), "r"(a[2]), "r"(a[3]), "r"(b0), "r"(b1));
}
__device__ __forceinline__ float fixf(float v){
    if (isnan(v)) return 0.f;
    if (isinf(v)) return v > 0.f ? 3.4028234663852886e38f : -3.4028234663852886e38f;
    return v;
}

// ----------------------------------------------------------------------------
// LayerNorm msa -> bufA (fp16)
__global__ void k_ln_msa(const float* __restrict__ msa,
                         const float* __restrict__ g,
                         const float* __restrict__ b){
    int warp = threadIdx.x >> 5, lane = threadIdx.x & 31;
    size_t row = (size_t)blockIdx.x * 8 + warp;
    const float* x = msa + row * DMSA;
    float v[8]; float s = 0.f;
    #pragma unroll
    for (int i = 0; i < 8; i++){ float t = fixf(x[lane + i*32]); v[i] = t; s += t; }
    #pragma unroll
    for (int o = 16; o; o >>= 1) s += __shfl_xor_sync(0xffffffffu, s, o);
    float mu = s * (1.f/256.f);
    float q = 0.f;
    #pragma unroll
    for (int i = 0; i < 8; i++){ float d0 = v[i] - mu; q += d0*d0; }
    #pragma unroll
    for (int o = 16; o; o >>= 1) q += __shfl_xor_sync(0xffffffffu, q, o);
    float rs = rsqrtf(q * (1.f/256.f) + EPSC);
    #pragma unroll
    for (int i = 0; i < 8; i++){
        int c = lane + i*32;
        g_bufA[row*DMSA + c] = __float2half_rn((v[i] - mu) * rs * g[c] + b[c]);
    }
}

// Weight transpose: g_wt[row=(z*256+j)][k] = W_z[k][j]
__global__ void k_conv_w(const float* __restrict__ wq, const float* __restrict__ wk,
                         const float* __restrict__ wv, const float* __restrict__ wg,
                         const float* __restrict__ wo){
    int row = blockIdx.x, kk = threadIdx.x;
    int z = row >> 8, j = row & 255;
    const float* src = (z==0)?wq:(z==1)?wk:(z==2)?wv:(z==3)?wg:wo;
    g_wt[(size_t)row*256 + kk] = __float2half_rn(src[kk*256 + j]);
}

// LayerNorm pair + bias GEMV
__global__ void k_pair_bias(const float* __restrict__ pair,
                            const float* __restrict__ g,
                            const float* __restrict__ b,
                            const float* __restrict__ wb){
    __shared__ float swb[Hh*DPAIR];
    for (int i = threadIdx.x; i < Hh*DPAIR; i += blockDim.x){
        int h = i / DPAIR, c = i % DPAIR;
        swb[i] = wb[c*Hh + h];
    }
    __syncthreads();
    int warp = threadIdx.x >> 5, lane = threadIdx.x & 31;
    size_t row = (size_t)blockIdx.x * 8 + warp;
    const float* x = pair + row * DPAIR;
    float v[4]; float s = 0.f;
    #pragma unroll
    for (int i = 0; i < 4; i++){ float t = fixf(x[lane + i*32]); v[i] = t; s += t; }
    #pragma unroll
    for (int o = 16; o; o >>= 1) s += __shfl_xor_sync(0xffffffffu, s, o);
    float mu = s * (1.f/128.f);
    float q = 0.f;
    #pragma unroll
    for (int i = 0; i < 4; i++){ float d0 = v[i] - mu; q += d0*d0; }
    #pragma unroll
    for (int o = 16; o; o >>= 1) q += __shfl_xor_sync(0xffffffffu, q, o);
    float rs = rsqrtf(q * (1.f/128.f) + EPSC);
    float acc[8] = {};
    #pragma unroll
    for (int i = 0; i < 4; i++){
        int c = lane + i*32;
        float pn = (v[i] - mu) * rs * g[c] + b[c];
        #pragma unroll
        for (int h = 0; h < 8; h++) acc[h] += pn * swb[h*DPAIR + c];
    }
    #pragma unroll
    for (int h = 0; h < 8; h++)
        #pragma unroll
        for (int o = 16; o; o >>= 1) acc[h] += __shfl_xor_sync(0xffffffffu, acc[h], o);
    float outv = 0.f;
    #pragma unroll
    for (int h = 0; h < 8; h++) if (lane == h) outv = acc[h];
    if (lane < 8) g_bias[row*Hh + lane] = outv;
}

// Transpose V: [h][l][nd] -> [h][nd][l] into bufA
__global__ void k_transpose_v(){
    __shared__ hf tile[32][33];
    int head = blockIdx.z;
    const hf* src = g_v + (size_t)head * Ln * NDIM;
    hf* dst = g_bufA + (size_t)head * NDIM * Ln;
    int nd0 = blockIdx.x * 32, l0 = blockIdx.y * 32;
    #pragma unroll
    for (int yy = 0; yy < 4; yy++)
        tile[threadIdx.y + yy*8][threadIdx.x] =
            src[(size_t)(l0 + threadIdx.y + yy*8) * NDIM + nd0 + threadIdx.x];
    __syncthreads();
    #pragma unroll
    for (int yy = 0; yy < 4; yy++)
        dst[(size_t)(nd0 + threadIdx.y + yy*8) * Ln + l0 + threadIdx.x] =
            tile[threadIdx.x][threadIdx.y + yy*8];
}

// Softmax over k with bias + mask; writes P as fp16
__global__ void k_softmax(const int* __restrict__ mask){
    int h = blockIdx.x >> 9, q = blockIdx.x & (Ln-1);
    const float* row = g_attn + ((size_t)h*Ln + q)*Ln;
    bool padq = (mask[q] == 0);
    int t = threadIdx.x;
    int k0 = t, k1 = t + 256;
    float v0 = (padq || mask[k0] == 0) ? -1e9f : row[k0] + g_bias[((size_t)q*Ln + k0)*Hh + h];
    float v1 = (padq || mask[k1] == 0) ? -1e9f : row[k1] + g_bias[((size_t)q*Ln + k1)*Hh + h];
    __shared__ float red[256];
    red[t] = fmaxf(v0, v1); __syncthreads();
    for (int s = 128; s > 0; s >>= 1){ if (t < s) red[t] = fmaxf(red[t], red[t+s]); __syncthreads(); }
    float m = red[0]; __syncthreads();
    float e0 = expf(v0 - m), e1 = expf(v1 - m);
    red[t] = e0 + e1; __syncthreads();
    for (int s = 128; s > 0; s >>= 1){ if (t < s) red[t] += red[t+s]; __syncthreads(); }
    float inv = 1.f / red[0];
    size_t base = ((size_t)h*Ln + q)*Ln;
    g_p[base + k0] = __float2half_rn(e0*inv);
    g_p[base + k1] = __float2half_rn(e1*inv);
}

// ----------------------------------------------------------------------------
// Warp-MMA GEMM. MODE: 0=QKVG, 1=attn logits, 2=AV, 3=out-proj
// D[BM=128, BN=64] = A[M,K] @ B[N,K]^T, fp16 K-major operands, fp32 accum.
// 8 warps: 4(M) x 2(N), each 32x32.  BK=64, double-buffered cp.async.
// SMEM row stride 72 halves (144B, 16B-aligned; i*36 words mod 32 distinct
// over 8 rows -> conflict-free ldmatrix).
#define RS   72
#define AELE 9216             // 128*72
#define BELE 4608             // 64*72
#define BUFE 13824            // A+B elems per buffer
#define SMEMB (2*BUFE*2)      // 55296 bytes

template<int MODE>
__global__ __launch_bounds__(256, 4) void k_mma(const int* __restrict__ mask,
                                                const float* __restrict__ bg,
                                                const float* __restrict__ bout,
                                                float* __restrict__ outp){
    extern __shared__ hf smem[];
    uint32_t sb = s2u(smem);
    int tid = threadIdx.x, wid = tid >> 5, lid = tid & 31;
    int wm = wid & 3, wn = wid >> 2;
    int h = blockIdx.z;
    int m0 = blockIdx.y * 128, n0 = blockIdx.x * 64;
    const int K   = (MODE==1) ? NDIM : (MODE==2) ? Ln : 256;
    const int nit = K / 64;

    const hf *A, *B; int lda = 0, ldb = 0;
    if (MODE == 0){
        A = g_bufA; lda = 256;
        B = g_wt;   ldb = 256;
    } else if (MODE == 1){
        size_t o = (size_t)h * Ln * NDIM;
        A = g_bufB + o; lda = NDIM;
        B = g_k + o;    ldb = NDIM;
    } else if (MODE == 2){
        A = g_p + (size_t)h * Ln * Ln; lda = Ln;
        B = g_bufA + (size_t)h * NDIM * Ln; ldb = Ln;
    } else {
        A = g_bufB; lda = 0;
        B = g_wt + 1024*256; ldb = 256;
    }

    float acc[2][4][4] = {};

    auto issue = [&](int it){
        int b = it & 1, kt = it * 64;
        #pragma unroll
        for (int t = 0; t < 4; t++){
            int q = tid + t*256;
            int r = q >> 3, cc = q & 7;
            uint32_t so = sb + 2*(b*BUFE + r*RS + cc*8);
            const hf* gp;
            if (MODE == 3){
                int row = m0 + r; int n = row >> 9, l = row & (Ln-1);
                int c0 = kt + cc*8; int hh = c0 >> 5, d0 = c0 & 31;
                gp = A + ((size_t)(hh*Ln + l))*NDIM + (n << 5) + d0;
            } else {
                gp = A + (size_t)(m0 + r)*lda + kt + cc*8;
            }
            CP16(so, gp);
        }
        #pragma unroll
        for (int t = 0; t < 2; t++){
            int q = tid + t*256;
            int r = q >> 3, cc = q & 7;
            uint32_t so = sb + 2*(b*BUFE + AELE + r*RS + cc*8);
            CP16(so, B + (size_t)(n0 + r)*ldb + kt + cc*8);
        }
        CPCOMMIT();
    };

    issue(0);
    for (int it = 0; it < nit; it++){
        if (it + 1 < nit){ issue(it + 1); CPWAIT(1); }
        else             { CPWAIT(0); }
        __syncthreads();
        int b = it & 1;
        #pragma unroll
        for (int kk = 0; kk < 4; kk++){
            uint32_t ah[2][4], bh[2][4];
            int lrow = lid & 15, lch = lid >> 4;
            #pragma unroll
            for (int mi = 0; mi < 2; mi++){
                uint32_t base = sb + 2*(b*BUFE + (wm*32 + mi*16 + lrow)*RS + kk*16 + lch*8);
                ldsm4(base, ah[mi]);
            }
            #pragma unroll
            for (int nj = 0; nj < 2; nj++){
                uint32_t base = sb + 2*(b*BUFE + AELE + (wn*32 + nj*16 + lrow)*RS + kk*16 + lch*8);
                ldsm4(base, bh[nj]);
            }
            #pragma unroll
            for (int mi = 0; mi < 2; mi++)
                #pragma unroll
                for (int ni = 0; ni < 4; ni++){
                    int nj = ni >> 1, sel = ni & 1;
                    mma16816(acc[mi][ni], ah[mi], bh[nj][sel], bh[nj][2+sel]);
                }
        }
        __syncthreads();
    }

    // epilogue (packed pair stores; cols (gcol, gcol+1) adjacent)
    int lr = lid >> 2, lc = (lid & 3)*2;
    #pragma unroll
    for (int mi = 0; mi < 2; mi++){
        #pragma unroll
        for (int ni = 0; ni < 4; ni++){
            int gcol = n0 + wn*32 + ni*8 + lc;
            #pragma unroll
            for (int half = 0; half < 2; half++){
                int row = m0 + wm*32 + mi*16 + lr + half*8;
                float v0 = acc[mi][ni][half*2 + 0];
                float v1 = acc[mi][ni][half*2 + 1];
                if (MODE == 0){
                    int z = gcol >> 8, j = gcol & 255;
                    int l = row & (Ln-1), n = row >> 9;
                    bool pad = (mask[l] == 0);
                    if (z == 3){
                        float2 gv;
                        gv.x = 1.f/(1.f + expf(-(v0 + bg[j])));
                        gv.y = 1.f/(1.f + expf(-(v1 + bg[j+1])));
                        *(float2*)&g_gate[(size_t)row*HD + j] = gv;
                    } else {
                        if (pad){ v0 = 0.f; v1 = 0.f; }
                        else if (z == 1){ v0 *= SCALING; v1 *= SCALING; }
                        int hh = j >> 5, d = j & 31;
                        size_t idx = ((size_t)(hh*Ln + l))*NDIM + (n << 5) + d;
                        __half2 hv = __floats2half2_rn(v0, v1);
                        if (z == 0)      *(__half2*)&g_bufB[idx] = hv;
                        else if (z == 1) *(__half2*)&g_k[idx] = hv;
                        else             *(__half2*)&g_v[idx] = hv;
                    }
                } else if (MODE == 1){
                    float2 fv; fv.x = v0; fv.y = v1;
                    *(float2*)&g_attn[((size_t)(h*Ln + row))*Ln + gcol] = fv;
                } else if (MODE == 2){
                    int n = gcol >> 5, d = gcol & 31;
                    float2 gt = *(const float2*)&g_gate[((size_t)(n*Ln + row))*HD + h*32 + d];
                    *(__half2*)&g_bufB[((size_t)(h*Ln + row))*NDIM + gcol] =
                        __floats2half2_rn(v0*gt.x, v1*gt.y);
                } else {
                    int l = row & (Ln-1);
                    bool pad = (mask[l] == 0);
                    float2 ov;
                    ov.x = pad ? 0.f : (v0 + bout[gcol]);
                    ov.y = pad ? 0.f : (v1 + bout[gcol+1]);
                    *(float2*)&outp[(size_t)row*HD + gcol] = ov;
                }
            }
        }
    }
}

// ----------------------------------------------------------------------------
extern "C" void kernel_launch(void* const* d_in, const int* in_sizes, int n_in,
                              void* d_out, int out_size){
    const float* msa      = (const float*)d_in[0];
    const float* pair     = (const float*)d_in[1];
    const float* ln_msa_g = (const float*)d_in[2];
    const float* ln_msa_b = (const float*)d_in[3];
    const float* ln_pr_g  = (const float*)d_in[4];
    const float* ln_pr_b  = (const float*)d_in[5];
    const float* w_q      = (const float*)d_in[6];
    const float* w_k      = (const float*)d_in[7];
    const float* w_v      = (const float*)d_in[8];
    const float* w_b      = (const float*)d_in[9];
    const float* w_g      = (const float*)d_in[10];
    const float* b_g      = (const float*)d_in[11];
    const float* w_out    = (const float*)d_in[12];
    const float* b_out    = (const float*)d_in[13];
    const int*   mask     = (const int*)  d_in[14];
    float* out = (float*)d_out;

    cudaFuncSetAttribute(k_mma<0>, cudaFuncAttributeMaxDynamicSharedMemorySize, SMEMB);
    cudaFuncSetAttribute(k_mma<1>, cudaFuncAttributeMaxDynamicSharedMemorySize, SMEMB);
    cudaFuncSetAttribute(k_mma<2>, cudaFuncAttributeMaxDynamicSharedMemorySize, SMEMB);
    cudaFuncSetAttribute(k_mma<3>, cudaFuncAttributeMaxDynamicSharedMemorySize, SMEMB);

    k_ln_msa   <<<NL/8, 256>>>(msa, ln_msa_g, ln_msa_b);
    k_conv_w   <<<1280, 256>>>(w_q, w_k, w_v, w_g, w_out);
    k_pair_bias<<<(Ln*Ln)/8, 256>>>(pair, ln_pr_g, ln_pr_b, w_b);
    k_mma<0>   <<<dim3(16, 1024, 1), 256, SMEMB>>>(mask, b_g, b_out, out);
    k_transpose_v<<<dim3(NDIM/32, Ln/32, 8), dim3(32, 8)>>>();
    k_mma<1>   <<<dim3(8, 4, 8),    256, SMEMB>>>(mask, b_g, b_out, out);
    k_softmax  <<<Hh*Ln, 256>>>(mask);
    k_mma<2>   <<<dim3(128, 4, 8),  256, SMEMB>>>(mask, b_g, b_out, out);
    k_mma<3>   <<<dim3(4, 1024, 1), 256, SMEMB>>>(mask, b_g, b_out, out);
}

// round 16
// speedup vs baseline: 3.7519x; 1.0171x over previous
#include <cuda_runtime.h>
#include <cuda_fp16.h>
#include <stdint.h>
#include <math.h>

// Problem dims
#define Ln 512
#define Nn 256
#define DMSA 256
#define DPAIR 128
#define Hh 8
#define Dd 32
#define HD 256
#define NL (Nn*Ln)          // 131072
#define NDIM 8192           // (n,d) contraction dim
#define SCALING 0.17677669529663689f
#define EPSC 1e-5f

typedef __half hf;

// ----------------------------------------------------------------------------
// Scratch (device globals). Aliasing:
//   g_bufA = msa_n  then  v^T     g_bufB = q  then  o
__device__ __align__(16) hf g_bufA[33554432];
__device__ __align__(16) hf g_bufB[33554432];
__device__ __align__(16) hf g_k[33554432];     // [h][l][nd]
__device__ __align__(16) hf g_v[33554432];     // [h][l][nd]
__device__ __align__(16) hf g_p[2097152];      // [h][q][k]
__device__ __align__(16) hf g_wt[327680];      // [1280][256]: 0..1023 wq|wk|wv|wg ^T, 1024..1279 w_out^T
__device__ float g_gate[33554432];             // [r=(n,l)][h*32+d]
__device__ float g_attn[2097152];              // [h][q][k]
__device__ float g_bias[2097152];              // [q][k][h]

// ----------------------------------------------------------------------------
__device__ __forceinline__ uint32_t s2u(const void* p){
    uint32_t a;
    asm("{ .reg .u64 t; cvta.to.shared.u64 t, %1; cvt.u32.u64 %0, t; }" : "=r"(a) : "l"(p));
    return a;
}
#define CP16(sa, gp) \
    asm volatile("cp.async.cg.shared.global [%0], [%1], 16;" :: "r"(sa), "l"(gp))
#define CPCOMMIT() asm volatile("cp.async.commit_group;" ::: "memory")
#define CPWAIT(n)  asm volatile("cp.async.wait_group %0;" :: "n"(n) : "memory")

__device__ __forceinline__ void ldsm4(uint32_t a, uint32_t r[4]){
    asm volatile("ldmatrix.sync.aligned.m8n8.x4.shared.b16 {%0,%1,%2,%3}, [%4];"
                 : "=r"(r[0]), "=r"(r[1]), "=r"(r[2]), "=r"(r[3]) : "r"(a));
}
__device__ __forceinline__ void mma16816(float c[4], const uint32_t a[4],
                                         uint32_t b0, uint32_t b1){
    asm volatile("mma.sync.aligned.m16n8k16.row.col.f32.f16.f16.f32 "
                 "{%0,%1,%2,%3}, {%4,%5,%6,%7}, {%8,%9}, {%0,%1,%2,%3};"
                 : "+f"(c[0]), "+f"(c[1]), "+f"(c[2]), "+f"(c[3])
                 : "r"(a[0]), "r"(a[1]), "r"(a[2]), "r"(a[3]), "r"(b0), "r"(b1));
}
__device__ __forceinline__ float fixf(float v){
    if (isnan(v)) return 0.f;
    if (isinf(v)) return v > 0.f ? 3.4028234663852886e38f : -3.4028234663852886e38f;
    return v;
}

// ----------------------------------------------------------------------------
// LayerNorm msa -> bufA (fp16)
__global__ void k_ln_msa(const float* __restrict__ msa,
                         const float* __restrict__ g,
                         const float* __restrict__ b){
    int warp = threadIdx.x >> 5, lane = threadIdx.x & 31;
    size_t row = (size_t)blockIdx.x * 8 + warp;
    const float* x = msa + row * DMSA;
    float v[8]; float s = 0.f;
    #pragma unroll
    for (int i = 0; i < 8; i++){ float t = fixf(x[lane + i*32]); v[i] = t; s += t; }
    #pragma unroll
    for (int o = 16; o; o >>= 1) s += __shfl_xor_sync(0xffffffffu, s, o);
    float mu = s * (1.f/256.f);
    float q = 0.f;
    #pragma unroll
    for (int i = 0; i < 8; i++){ float d0 = v[i] - mu; q += d0*d0; }
    #pragma unroll
    for (int o = 16; o; o >>= 1) q += __shfl_xor_sync(0xffffffffu, q, o);
    float rs = rsqrtf(q * (1.f/256.f) + EPSC);
    #pragma unroll
    for (int i = 0; i < 8; i++){
        int c = lane + i*32;
        g_bufA[row*DMSA + c] = __float2half_rn((v[i] - mu) * rs * g[c] + b[c]);
    }
}

// Weight transpose: g_wt[row=(z*256+j)][k] = W_z[k][j]
__global__ void k_conv_w(const float* __restrict__ wq, const float* __restrict__ wk,
                         const float* __restrict__ wv, const float* __restrict__ wg,
                         const float* __restrict__ wo){
    int row = blockIdx.x, kk = threadIdx.x;
    int z = row >> 8, j = row & 255;
    const float* src = (z==0)?wq:(z==1)?wk:(z==2)?wv:(z==3)?wg:wo;
    g_wt[(size_t)row*256 + kk] = __float2half_rn(src[kk*256 + j]);
}

// LayerNorm pair + bias GEMV
__global__ void k_pair_bias(const float* __restrict__ pair,
                            const float* __restrict__ g,
                            const float* __restrict__ b,
                            const float* __restrict__ wb){
    __shared__ float swb[Hh*DPAIR];
    for (int i = threadIdx.x; i < Hh*DPAIR; i += blockDim.x){
        int h = i / DPAIR, c = i % DPAIR;
        swb[i] = wb[c*Hh + h];
    }
    __syncthreads();
    int warp = threadIdx.x >> 5, lane = threadIdx.x & 31;
    size_t row = (size_t)blockIdx.x * 8 + warp;
    const float* x = pair + row * DPAIR;
    float v[4]; float s = 0.f;
    #pragma unroll
    for (int i = 0; i < 4; i++){ float t = fixf(x[lane + i*32]); v[i] = t; s += t; }
    #pragma unroll
    for (int o = 16; o; o >>= 1) s += __shfl_xor_sync(0xffffffffu, s, o);
    float mu = s * (1.f/128.f);
    float q = 0.f;
    #pragma unroll
    for (int i = 0; i < 4; i++){ float d0 = v[i] - mu; q += d0*d0; }
    #pragma unroll
    for (int o = 16; o; o >>= 1) q += __shfl_xor_sync(0xffffffffu, q, o);
    float rs = rsqrtf(q * (1.f/128.f) + EPSC);
    float acc[8] = {};
    #pragma unroll
    for (int i = 0; i < 4; i++){
        int c = lane + i*32;
        float pn = (v[i] - mu) * rs * g[c] + b[c];
        #pragma unroll
        for (int h = 0; h < 8; h++) acc[h] += pn * swb[h*DPAIR + c];
    }
    #pragma unroll
    for (int h = 0; h < 8; h++)
        #pragma unroll
        for (int o = 16; o; o >>= 1) acc[h] += __shfl_xor_sync(0xffffffffu, acc[h], o);
    float outv = 0.f;
    #pragma unroll
    for (int h = 0; h < 8; h++) if (lane == h) outv = acc[h];
    if (lane < 8) g_bias[row*Hh + lane] = outv;
}

// Transpose V: [h][l][nd] -> [h][nd][l] into bufA
__global__ void k_transpose_v(){
    __shared__ hf tile[32][33];
    int head = blockIdx.z;
    const hf* src = g_v + (size_t)head * Ln * NDIM;
    hf* dst = g_bufA + (size_t)head * NDIM * Ln;
    int nd0 = blockIdx.x * 32, l0 = blockIdx.y * 32;
    #pragma unroll
    for (int yy = 0; yy < 4; yy++)
        tile[threadIdx.y + yy*8][threadIdx.x] =
            src[(size_t)(l0 + threadIdx.y + yy*8) * NDIM + nd0 + threadIdx.x];
    __syncthreads();
    #pragma unroll
    for (int yy = 0; yy < 4; yy++)
        dst[(size_t)(nd0 + threadIdx.y + yy*8) * Ln + l0 + threadIdx.x] =
            tile[threadIdx.x][threadIdx.y + yy*8];
}

// Softmax over k with bias + mask; writes P as fp16
__global__ void k_softmax(const int* __restrict__ mask){
    int h = blockIdx.x >> 9, q = blockIdx.x & (Ln-1);
    const float* row = g_attn + ((size_t)h*Ln + q)*Ln;
    bool padq = (mask[q] == 0);
    int t = threadIdx.x;
    int k0 = t, k1 = t + 256;
    float v0 = (padq || mask[k0] == 0) ? -1e9f : row[k0] + g_bias[((size_t)q*Ln + k0)*Hh + h];
    float v1 = (padq || mask[k1] == 0) ? -1e9f : row[k1] + g_bias[((size_t)q*Ln + k1)*Hh + h];
    __shared__ float red[256];
    red[t] = fmaxf(v0, v1); __syncthreads();
    for (int s = 128; s > 0; s >>= 1){ if (t < s) red[t] = fmaxf(red[t], red[t+s]); __syncthreads(); }
    float m = red[0]; __syncthreads();
    float e0 = expf(v0 - m), e1 = expf(v1 - m);
    red[t] = e0 + e1; __syncthreads();
    for (int s = 128; s > 0; s >>= 1){ if (t < s) red[t] += red[t+s]; __syncthreads(); }
    float inv = 1.f / red[0];
    size_t base = ((size_t)h*Ln + q)*Ln;
    g_p[base + k0] = __float2half_rn(e0*inv);
    g_p[base + k1] = __float2half_rn(e1*inv);
}

// ----------------------------------------------------------------------------
// Warp-MMA GEMM. MODE: 0=QKVG, 1=attn logits, 2=AV, 3=out-proj
// D[BM=128, BN] = A[M,K] @ B[N,K]^T, fp16 K-major operands, fp32 accum.
// 8 warps: 4(M) x 2(N), warp tile 32 x (BN/2).  BK=64, double-buffered cp.async.
// BN=128 for modes 0/2/3 (reuse-heavy); BN=64 for mode 1 (keeps grid >= SM count).
// SMEM row stride 72 halves (144B, 16B-aligned; conflict-free ldmatrix).
#define RS   72
#define AELE (128*RS)

template<int MODE, int BN>
__global__ __launch_bounds__(256, (BN==64) ? 4 : 2)
void k_mma(const int* __restrict__ mask,
           const float* __restrict__ bg,
           const float* __restrict__ bout,
           float* __restrict__ outp){
    constexpr int BELE = BN*RS;
    constexpr int BUFE = AELE + BELE;
    constexpr int NJ   = BN/32;      // 16-row B groups per warp tile
    constexpr int NI   = BN/16;      // 8-col output groups per warp tile
    extern __shared__ hf smem[];
    uint32_t sb = s2u(smem);
    int tid = threadIdx.x, wid = tid >> 5, lid = tid & 31;
    int wm = wid & 3, wn = wid >> 2;
    int h = blockIdx.z;
    int m0 = blockIdx.y * 128, n0 = blockIdx.x * BN;
    const int K   = (MODE==1) ? NDIM : (MODE==2) ? Ln : 256;
    const int nit = K / 64;

    const hf *A, *B; int lda = 0, ldb = 0;
    if (MODE == 0){
        A = g_bufA; lda = 256;
        B = g_wt;   ldb = 256;
    } else if (MODE == 1){
        size_t o = (size_t)h * Ln * NDIM;
        A = g_bufB + o; lda = NDIM;
        B = g_k + o;    ldb = NDIM;
    } else if (MODE == 2){
        A = g_p + (size_t)h * Ln * Ln; lda = Ln;
        B = g_bufA + (size_t)h * NDIM * Ln; ldb = Ln;
    } else {
        A = g_bufB; lda = 0;
        B = g_wt + 1024*256; ldb = 256;
    }

    float acc[2][NI][4] = {};

    auto issue = [&](int it){
        int b = it & 1, kt = it * 64;
        #pragma unroll
        for (int t = 0; t < 4; t++){
            int q = tid + t*256;
            int r = q >> 3, cc = q & 7;
            uint32_t so = sb + 2*(b*BUFE + r*RS + cc*8);
            const hf* gp;
            if (MODE == 3){
                int row = m0 + r; int n = row >> 9, l = row & (Ln-1);
                int c0 = kt + cc*8; int hh = c0 >> 5, d0 = c0 & 31;
                gp = A + ((size_t)(hh*Ln + l))*NDIM + (n << 5) + d0;
            } else {
                gp = A + (size_t)(m0 + r)*lda + kt + cc*8;
            }
            CP16(so, gp);
        }
        #pragma unroll
        for (int t = 0; t < BN/32; t++){
            int q = tid + t*256;
            int r = q >> 3, cc = q & 7;
            uint32_t so = sb + 2*(b*BUFE + AELE + r*RS + cc*8);
            CP16(so, B + (size_t)(n0 + r)*ldb + kt + cc*8);
        }
        CPCOMMIT();
    };

    issue(0);
    for (int it = 0; it < nit; it++){
        if (it + 1 < nit){ issue(it + 1); CPWAIT(1); }
        else             { CPWAIT(0); }
        __syncthreads();
        int b = it & 1;
        #pragma unroll
        for (int kk = 0; kk < 4; kk++){
            uint32_t ah[2][4], bh[NJ][4];
            int lrow = lid & 15, lch = lid >> 4;
            #pragma unroll
            for (int mi = 0; mi < 2; mi++){
                uint32_t base = sb + 2*(b*BUFE + (wm*32 + mi*16 + lrow)*RS + kk*16 + lch*8);
                ldsm4(base, ah[mi]);
            }
            #pragma unroll
            for (int nj = 0; nj < NJ; nj++){
                uint32_t base = sb + 2*(b*BUFE + AELE + (wn*(BN/2) + nj*16 + lrow)*RS + kk*16 + lch*8);
                ldsm4(base, bh[nj]);
            }
            #pragma unroll
            for (int mi = 0; mi < 2; mi++)
                #pragma unroll
                for (int ni = 0; ni < NI; ni++){
                    int nj = ni >> 1, sel = ni & 1;
                    mma16816(acc[mi][ni], ah[mi], bh[nj][sel], bh[nj][2+sel]);
                }
        }
        __syncthreads();
    }

    // epilogue (packed pair stores; cols (gcol, gcol+1) adjacent)
    int lr = lid >> 2, lc = (lid & 3)*2;
    #pragma unroll
    for (int mi = 0; mi < 2; mi++){
        #pragma unroll
        for (int ni = 0; ni < NI; ni++){
            int gcol = n0 + wn*(BN/2) + ni*8 + lc;
            #pragma unroll
            for (int half = 0; half < 2; half++){
                int row = m0 + wm*32 + mi*16 + lr + half*8;
                float v0 = acc[mi][ni][half*2 + 0];
                float v1 = acc[mi][ni][half*2 + 1];
                if (MODE == 0){
                    int z = gcol >> 8, j = gcol & 255;
                    int l = row & (Ln-1), n = row >> 9;
                    bool pad = (mask[l] == 0);
                    if (z == 3){
                        float2 gv;
                        gv.x = 1.f/(1.f + expf(-(v0 + bg[j])));
                        gv.y = 1.f/(1.f + expf(-(v1 + bg[j+1])));
                        *(float2*)&g_gate[(size_t)row*HD + j] = gv;
                    } else {
                        if (pad){ v0 = 0.f; v1 = 0.f; }
                        else if (z == 1){ v0 *= SCALING; v1 *= SCALING; }
                        int hh = j >> 5, d = j & 31;
                        size_t idx = ((size_t)(hh*Ln + l))*NDIM + (n << 5) + d;
                        __half2 hv = __floats2half2_rn(v0, v1);
                        if (z == 0)      *(__half2*)&g_bufB[idx] = hv;
                        else if (z == 1) *(__half2*)&g_k[idx] = hv;
                        else             *(__half2*)&g_v[idx] = hv;
                    }
                } else if (MODE == 1){
                    float2 fv; fv.x = v0; fv.y = v1;
                    *(float2*)&g_attn[((size_t)(h*Ln + row))*Ln + gcol] = fv;
                } else if (MODE == 2){
                    int n = gcol >> 5, d = gcol & 31;
                    float2 gt = *(const float2*)&g_gate[((size_t)(n*Ln + row))*HD + h*32 + d];
                    *(__half2*)&g_bufB[((size_t)(h*Ln + row))*NDIM + gcol] =
                        __floats2half2_rn(v0*gt.x, v1*gt.y);
                } else {
                    int l = row & (Ln-1);
                    bool pad = (mask[l] == 0);
                    float2 ov;
                    ov.x = pad ? 0.f : (v0 + bout[gcol]);
                    ov.y = pad ? 0.f : (v1 + bout[gcol+1]);
                    *(float2*)&outp[(size_t)row*HD + gcol] = ov;
                }
            }
        }
    }
}

// ----------------------------------------------------------------------------
extern "C" void kernel_launch(void* const* d_in, const int* in_sizes, int n_in,
                              void* d_out, int out_size){
    const float* msa      = (const float*)d_in[0];
    const float* pair     = (const float*)d_in[1];
    const float* ln_msa_g = (const float*)d_in[2];
    const float* ln_msa_b = (const float*)d_in[3];
    const float* ln_pr_g  = (const float*)d_in[4];
    const float* ln_pr_b  = (const float*)d_in[5];
    const float* w_q      = (const float*)d_in[6];
    const float* w_k      = (const float*)d_in[7];
    const float* w_v      = (const float*)d_in[8];
    const float* w_b      = (const float*)d_in[9];
    const float* w_g      = (const float*)d_in[10];
    const float* b_g      = (const float*)d_in[11];
    const float* w_out    = (const float*)d_in[12];
    const float* b_out    = (const float*)d_in[13];
    const int*   mask     = (const int*)  d_in[14];
    float* out = (float*)d_out;

    const int SM64  = 2*(AELE + 64*RS)*2;    // 55296
    const int SM128 = 2*(AELE + 128*RS)*2;   // 73728
    cudaFuncSetAttribute(k_mma<0,128>, cudaFuncAttributeMaxDynamicSharedMemorySize, SM128);
    cudaFuncSetAttribute(k_mma<1,64>,  cudaFuncAttributeMaxDynamicSharedMemorySize, SM64);
    cudaFuncSetAttribute(k_mma<2,128>, cudaFuncAttributeMaxDynamicSharedMemorySize, SM128);
    cudaFuncSetAttribute(k_mma<3,128>, cudaFuncAttributeMaxDynamicSharedMemorySize, SM128);

    k_ln_msa   <<<NL/8, 256>>>(msa, ln_msa_g, ln_msa_b);
    k_conv_w   <<<1280, 256>>>(w_q, w_k, w_v, w_g, w_out);
    k_pair_bias<<<(Ln*Ln)/8, 256>>>(pair, ln_pr_g, ln_pr_b, w_b);
    k_mma<0,128><<<dim3(8, 1024, 1), 256, SM128>>>(mask, b_g, b_out, out);
    k_transpose_v<<<dim3(NDIM/32, Ln/32, 8), dim3(32, 8)>>>();
    k_mma<1,64> <<<dim3(8, 4, 8),    256, SM64>>> (mask, b_g, b_out, out);
    k_softmax  <<<Hh*Ln, 256>>>(mask);
    k_mma<2,128><<<dim3(64, 4, 8),   256, SM128>>>(mask, b_g, b_out, out);
    k_mma<3,128><<<dim3(2, 1024, 1), 256, SM128>>>(mask, b_g, b_out, out);
}